// round 1
// baseline (speedup 1.0000x reference)
#include <cuda_runtime.h>
#include <cuda_bf16.h>
#include <cstdint>

// Problem constants (fixed by the reference)
#define NB 32      // batch
#define NZ 4000    // nodes
#define NIN 32     // in features
#define NH 64      // hidden
#define NE 64000   // edges

// Scratch (device globals; no allocations allowed)
__device__ float g_y[NZ * NB];     // y[z*NB + b] = x[b,z,:] . v   (transposed layout)
__device__ float g_acc[NZ * NB];   // accumulator, [z][b]
__device__ int   g_deg[NZ];
__device__ float g_dinv[NZ];
__device__ float g_v[NIN];         // W @ fc_W
__device__ float g_const;          // b . fc_W + fc_b

// ---------------------------------------------------------------------------
// K1: deg[z] = 1 (self-loop); block 0 also computes v = W@fc_W and the const.
// ---------------------------------------------------------------------------
__global__ void k_init(const float* __restrict__ W,
                       const float* __restrict__ bias,
                       const float* __restrict__ fcW,
                       const float* __restrict__ fcb) {
    int t = blockIdx.x * blockDim.x + threadIdx.x;
    if (t < NZ) g_deg[t] = 1;
    if (blockIdx.x == 0) {
        if (threadIdx.x < NIN) {
            float s = 0.f;
            #pragma unroll
            for (int h = 0; h < NH; ++h) s += W[threadIdx.x * NH + h] * fcW[h];
            g_v[threadIdx.x] = s;
        } else if (threadIdx.x == NIN) {
            float s = fcb[0];
            #pragma unroll
            for (int h = 0; h < NH; ++h) s += bias[h] * fcW[h];
            g_const = s;
        }
    }
}

// ---------------------------------------------------------------------------
// K2: in-degree histogram over edge destinations.
// ---------------------------------------------------------------------------
__global__ void k_deg(const int* __restrict__ dst) {
    int e = blockIdx.x * blockDim.x + threadIdx.x;
    if (e < NE) atomicAdd(&g_deg[dst[e]], 1);
}

// ---------------------------------------------------------------------------
// K3: dinv = rsqrt(deg)   (deg >= 1 always due to self-loop)
// ---------------------------------------------------------------------------
__global__ void k_dinv() {
    int z = blockIdx.x * blockDim.x + threadIdx.x;
    if (z < NZ) g_dinv[z] = rsqrtf((float)g_deg[z]);
}

// ---------------------------------------------------------------------------
// K4: y[z,b] = x[b,z,:] . v ; acc[z,b] = dinv[z]^2 * y[z,b]  (self-loop term)
// One thread per (z, b): lane = b, so a warp shares one z.
// ---------------------------------------------------------------------------
__global__ void k_ydot(const float* __restrict__ x) {
    int t = blockIdx.x * blockDim.x + threadIdx.x;   // t = z*32 + b
    if (t >= NZ * NB) return;
    int z = t >> 5;
    int b = t & 31;

    const float4* xp = reinterpret_cast<const float4*>(x) +
                       ((size_t)b * NZ + z) * (NIN / 4);
    const float4* vp = reinterpret_cast<const float4*>(g_v);

    float dot = 0.f;
    #pragma unroll
    for (int j = 0; j < NIN / 4; ++j) {
        float4 a = xp[j];
        float4 v = vp[j];
        dot += a.x * v.x + a.y * v.y + a.z * v.z + a.w * v.w;
    }
    float di = g_dinv[z];
    g_y[t]   = dot;
    g_acc[t] = di * di * dot;
}

// ---------------------------------------------------------------------------
// K5: edge scatter. Warp per edge, lane per batch.
// acc[dst, b] += dinv[src]*dinv[dst] * y[src, b]
// y/acc/dinv are L2-resident (~1 MB total). Atomic lines are coalesced 128B.
// ---------------------------------------------------------------------------
__global__ void k_scatter(const int* __restrict__ src,
                          const int* __restrict__ dst) {
    int t = blockIdx.x * blockDim.x + threadIdx.x;   // t = e*32 + lane
    if (t >= NE * NB) return;
    int e    = t >> 5;
    int lane = t & 31;
    int s = src[e];            // uniform across warp -> broadcast load
    int d = dst[e];
    float norm = g_dinv[s] * g_dinv[d];
    atomicAdd(&g_acc[d * NB + lane], norm * g_y[s * NB + lane]);
}

// ---------------------------------------------------------------------------
// K6: transpose acc[z][b] -> out[b][z], add const. 32x32 smem tile.
// ---------------------------------------------------------------------------
__global__ void k_out(float* __restrict__ out) {
    __shared__ float tile[32][33];
    int zb = blockIdx.x * 32;                 // NZ % 32 == 0 (4000 = 125*32)
    // coalesced read: warp = fixed ty (= z row), lanes tx over b
    tile[threadIdx.y][threadIdx.x] = g_acc[(zb + threadIdx.y) * NB + threadIdx.x];
    __syncthreads();
    float c = g_const;
    // thread (tx,ty): b = ty, z = zb + tx ; coalesced write along tx
    out[(size_t)threadIdx.y * NZ + zb + threadIdx.x] = tile[threadIdx.x][threadIdx.y] + c;
}

// ---------------------------------------------------------------------------
extern "C" void kernel_launch(void* const* d_in, const int* in_sizes, int n_in,
                              void* d_out, int out_size) {
    const float* x    = (const float*)d_in[0];   // [32,4000,32]
    const int*   ei   = (const int*)  d_in[1];   // [2,64000]
    const float* W    = (const float*)d_in[2];   // [32,64]
    const float* bias = (const float*)d_in[3];   // [64]
    const float* fcW  = (const float*)d_in[4];   // [64]
    const float* fcb  = (const float*)d_in[5];   // [1]
    float* out = (float*)d_out;                  // [32,4000]

    const int* src = ei;
    const int* dst = ei + NE;

    k_init<<<(NZ + 255) / 256, 256>>>(W, bias, fcW, fcb);
    k_deg<<<(NE + 255) / 256, 256>>>(dst);
    k_dinv<<<(NZ + 255) / 256, 256>>>();
    k_ydot<<<(NZ * NB + 255) / 256, 256>>>(x);
    k_scatter<<<(NE * NB + 255) / 256, 256>>>(src, dst);
    k_out<<<NZ / 32, dim3(32, 32)>>>(out);
}

// round 2
// speedup vs baseline: 1.1015x; 1.1015x over previous
#include <cuda_runtime.h>
#include <cuda_bf16.h>
#include <cstdint>

// Problem constants (fixed by the reference)
#define NB 32      // batch
#define NZ 4000    // nodes
#define NIN 32     // in features
#define NH 64      // hidden
#define NE 64000   // edges

// Scratch (device globals; no allocations allowed)
__device__ float g_y[NZ * NB];     // y[z*NB + b] = x[b,z,:] . v   (transposed layout)
__device__ float g_acc[NZ * NB];   // accumulator, [z][b]
__device__ int   g_deg[NZ];        // in-degree incl. self-loop
__device__ float g_v[NIN];         // W @ fc_W
__device__ float g_const;          // b . fc_W + fc_b

// ---------------------------------------------------------------------------
// K1: deg[z] = 1 (self-loop); block 0 also computes v = W@fc_W and the const.
// ---------------------------------------------------------------------------
__global__ void k_init(const float* __restrict__ W,
                       const float* __restrict__ bias,
                       const float* __restrict__ fcW,
                       const float* __restrict__ fcb) {
    int t = blockIdx.x * blockDim.x + threadIdx.x;
    if (t < NZ) g_deg[t] = 1;
    if (blockIdx.x == 0) {
        if (threadIdx.x < NIN) {
            float s = 0.f;
            #pragma unroll
            for (int h = 0; h < NH; ++h) s += W[threadIdx.x * NH + h] * fcW[h];
            g_v[threadIdx.x] = s;
        } else if (threadIdx.x == NIN) {
            float s = fcb[0];
            #pragma unroll
            for (int h = 0; h < NH; ++h) s += bias[h] * fcW[h];
            g_const = s;
        }
    }
}

// ---------------------------------------------------------------------------
// K2: in-degree histogram over edge destinations.
// ---------------------------------------------------------------------------
__global__ void k_deg(const int* __restrict__ dst) {
    int e = blockIdx.x * blockDim.x + threadIdx.x;
    if (e < NE) atomicAdd(&g_deg[dst[e]], 1);
}

// ---------------------------------------------------------------------------
// K3: fully-coalesced y-dot.
// Thread t loads float4 #t of x (flat, perfectly coalesced). Lanes 8k..8k+7
// cover one (b,z) row (NIN=32 floats = 8 float4). 3-step xor-shuffle reduce
// within the aligned 8-lane group; leader lane writes y and the self-loop
// accumulator term acc = y / deg  (== dinv^2 * y).
// ---------------------------------------------------------------------------
__global__ void k_ydot(const float* __restrict__ x) {
    int t = blockIdx.x * blockDim.x + threadIdx.x;   // < NB*NZ*NIN/4
    float4 xv = reinterpret_cast<const float4*>(x)[t];
    float4 vv = reinterpret_cast<const float4*>(g_v)[t & 7];
    float p = xv.x * vv.x + xv.y * vv.y + xv.z * vv.z + xv.w * vv.w;
    p += __shfl_xor_sync(0xFFFFFFFFu, p, 1);
    p += __shfl_xor_sync(0xFFFFFFFFu, p, 2);
    p += __shfl_xor_sync(0xFFFFFFFFu, p, 4);
    if ((t & 7) == 0) {
        int f = t >> 3;             // row index = b*NZ + z
        int b = f / NZ;
        int z = f - b * NZ;
        float invdeg = 1.0f / (float)g_deg[z];
        g_y[z * NB + b]   = p;
        g_acc[z * NB + b] = p * invdeg;
    }
}

// ---------------------------------------------------------------------------
// K4: edge scatter. Warp per edge, lane per batch.
// acc[dst, b] += rsqrt(deg[src]*deg[dst]) * y[src, b]
// y/acc/deg are L2-resident (~1 MB total). Atomic lines are coalesced 128B.
// ---------------------------------------------------------------------------
__global__ void k_scatter(const int* __restrict__ src,
                          const int* __restrict__ dst) {
    int t = blockIdx.x * blockDim.x + threadIdx.x;   // t = e*32 + lane
    if (t >= NE * NB) return;
    int e    = t >> 5;
    int lane = t & 31;
    int s = src[e];            // uniform across warp -> broadcast load
    int d = dst[e];
    float norm = rsqrtf((float)(g_deg[s] * g_deg[d]));
    atomicAdd(&g_acc[d * NB + lane], norm * g_y[s * NB + lane]);
}

// ---------------------------------------------------------------------------
// K5: transpose acc[z][b] -> out[b][z], add const. 32x32 smem tile.
// ---------------------------------------------------------------------------
__global__ void k_out(float* __restrict__ out) {
    __shared__ float tile[32][33];
    int zb = blockIdx.x * 32;                 // NZ % 32 == 0 (4000 = 125*32)
    tile[threadIdx.y][threadIdx.x] = g_acc[(zb + threadIdx.y) * NB + threadIdx.x];
    __syncthreads();
    float c = g_const;
    out[(size_t)threadIdx.y * NZ + zb + threadIdx.x] = tile[threadIdx.x][threadIdx.y] + c;
}

// ---------------------------------------------------------------------------
extern "C" void kernel_launch(void* const* d_in, const int* in_sizes, int n_in,
                              void* d_out, int out_size) {
    const float* x    = (const float*)d_in[0];   // [32,4000,32]
    const int*   ei   = (const int*)  d_in[1];   // [2,64000]
    const float* W    = (const float*)d_in[2];   // [32,64]
    const float* bias = (const float*)d_in[3];   // [64]
    const float* fcW  = (const float*)d_in[4];   // [64]
    const float* fcb  = (const float*)d_in[5];   // [1]
    float* out = (float*)d_out;                  // [32,4000]

    const int* src = ei;
    const int* dst = ei + NE;

    k_init<<<(NZ + 255) / 256, 256>>>(W, bias, fcW, fcb);
    k_deg<<<(NE + 255) / 256, 256>>>(dst);
    k_ydot<<<(NB * NZ * (NIN / 4)) / 256, 256>>>(x);
    k_scatter<<<(NE * NB + 255) / 256, 256>>>(src, dst);
    k_out<<<NZ / 32, dim3(32, 32)>>>(out);
}